// round 16
// baseline (speedup 1.0000x reference)
#include <cuda_runtime.h>
#include <cuda_fp16.h>
#include <cstdint>

#define FDIM 128
#define MAX_NODES 100000
#define MAX_EDGES 1600000
#define SCAN_B 1024
#define MAX_SCAN_BLOCKS ((MAX_NODES + SCAN_B - 1) / SCAN_B)

// ---------------- scratch (device globals: allocation-free rule) ----------------
__device__ __align__(16) __half g_hA[(size_t)MAX_NODES * FDIM];
__device__ __align__(16) __half g_hB[(size_t)MAX_NODES * FDIM];
__device__ float g_isq[MAX_NODES];
__device__ int   g_cnt[MAX_NODES];
__device__ int   g_lpos[MAX_EDGES];
__device__ int   g_rowptr[MAX_NODES + 1];
__device__ int   g_partial[MAX_SCAN_BLOCKS + 1];
__device__ int2  g_epack[MAX_EDGES];
// fragment-major B images: slot[(wc,ks,nt,lane)] = uint2{b0,b1}
__device__ __align__(16) uint2 g_wt1f[4096];   // N=128: 2*8*8*32
__device__ __align__(16) uint2 g_wt2f[4096];
__device__ __align__(16) uint2 g_wtff[2048];   // N=64 (fused W3@Wout)
__device__ float g_bf[64];                      // fused b3@Wout + bout

// ---------------- CSR build ----------------
__global__ void zero_kernel(int* __restrict__ cnt, int n) {
    int i = blockIdx.x * blockDim.x + threadIdx.x;
    if (i < n) cnt[i] = 0;
}
// scalar fallback
__global__ void count_kernel(const int* __restrict__ dst, int* __restrict__ cnt,
                             int* __restrict__ lpos, int E) {
    int e = blockIdx.x * blockDim.x + threadIdx.x;
    if (e < E) lpos[e] = atomicAdd(&cnt[dst[e]], 1);
}
// 4 edges/thread: int4 loads, 4 independent atomics (MLP x4)
__global__ void count4_kernel(const int* __restrict__ dst, int* __restrict__ cnt,
                              int* __restrict__ lpos, int E4) {
    int i = blockIdx.x * blockDim.x + threadIdx.x;
    if (i >= E4) return;
    int4 d = ((const int4*)dst)[i];
    int p0 = atomicAdd(&cnt[d.x], 1);
    int p1 = atomicAdd(&cnt[d.y], 1);
    int p2 = atomicAdd(&cnt[d.z], 1);
    int p3 = atomicAdd(&cnt[d.w], 1);
    ((int4*)lpos)[i] = make_int4(p0, p1, p2, p3);
}
// block scan + isq fused (both read cnt)
__global__ void block_scan_kernel(const int* __restrict__ cnt, int* __restrict__ rowptr,
                                  int* __restrict__ partial, float* __restrict__ isq, int n) {
    __shared__ int sh[SCAN_B];
    int i = blockIdx.x * SCAN_B + threadIdx.x;
    int v = (i < n) ? cnt[i] : 0;
    if (i < n) isq[i] = rsqrtf((float)(v + 1));
    sh[threadIdx.x] = v;
    __syncthreads();
#pragma unroll
    for (int off = 1; off < SCAN_B; off <<= 1) {
        int t = (threadIdx.x >= off) ? sh[threadIdx.x - off] : 0;
        __syncthreads();
        sh[threadIdx.x] += t;
        __syncthreads();
    }
    if (i < n) rowptr[i] = sh[threadIdx.x] - v;
    if (threadIdx.x == SCAN_B - 1) partial[blockIdx.x] = sh[SCAN_B - 1];
}
__global__ void partial_scan_kernel(int* __restrict__ partial, int nb) {
    int lane = threadIdx.x;   // 32 threads
    int base = lane * 4;
    int v0 = (base + 0 < nb) ? partial[base + 0] : 0;
    int v1 = (base + 1 < nb) ? partial[base + 1] : 0;
    int v2 = (base + 2 < nb) ? partial[base + 2] : 0;
    int v3 = (base + 3 < nb) ? partial[base + 3] : 0;
    int tot = v0 + v1 + v2 + v3;
    int x = tot;
#pragma unroll
    for (int off = 1; off < 32; off <<= 1) {
        int y = __shfl_up_sync(0xFFFFFFFF, x, off);
        if (lane >= off) x += y;
    }
    int run = x - tot;
    if (base + 0 < nb) partial[base + 0] = run;            run += v0;
    if (base + 1 < nb) partial[base + 1] = run;            run += v1;
    if (base + 2 < nb) partial[base + 2] = run;            run += v2;
    if (base + 3 < nb) partial[base + 3] = run;
    if (lane == 31) partial[nb] = x;
}
__global__ void add_offsets_kernel(int* __restrict__ rowptr, const int* __restrict__ partial,
                                   int n, int nb) {
    int i = blockIdx.x * blockDim.x + threadIdx.x;
    if (i < n) rowptr[i] += partial[i / SCAN_B];
    if (i == 0) rowptr[n] = partial[nb];
}
// scalar fallback
__global__ void fill_kernel(const int* __restrict__ src, const int* __restrict__ dst,
                            const float* __restrict__ isq, const int* __restrict__ rowptr,
                            const int* __restrict__ lpos, int2* __restrict__ epack, int E) {
    int e = blockIdx.x * blockDim.x + threadIdx.x;
    if (e >= E) return;
    int s = src[e], d = dst[e];
    epack[rowptr[d] + lpos[e]] = make_int2(s, __float_as_int(isq[s] * isq[d]));
}
// 4 edges/thread
__global__ void fill4_kernel(const int* __restrict__ src, const int* __restrict__ dst,
                             const float* __restrict__ isq, const int* __restrict__ rowptr,
                             const int* __restrict__ lpos, int2* __restrict__ epack, int E4) {
    int i = blockIdx.x * blockDim.x + threadIdx.x;
    if (i >= E4) return;
    int4 s4 = ((const int4*)src)[i];
    int4 d4 = ((const int4*)dst)[i];
    int4 l4 = ((const int4*)lpos)[i];
    epack[rowptr[d4.x] + l4.x] = make_int2(s4.x, __float_as_int(isq[s4.x] * isq[d4.x]));
    epack[rowptr[d4.y] + l4.y] = make_int2(s4.y, __float_as_int(isq[s4.y] * isq[d4.y]));
    epack[rowptr[d4.z] + l4.z] = make_int2(s4.z, __float_as_int(isq[s4.z] * isq[d4.z]));
    epack[rowptr[d4.w] + l4.w] = make_int2(s4.w, __float_as_int(isq[s4.w] * isq[d4.w]));
}

// ---------------- W prep: build fragment-major images --------------------------
// slot flat idx = wc*2048 + ks*256 + nt*32 + lane
//   n  = wc*64 + nt*8 + (lane>>2)
//   k0 = ks*16 + 2*(lane&3)
//   .x = half2(W[k0][n], W[k0+1][n]) ; .y = half2(W[k0+8][n], W[k0+9][n])
__global__ void prep_all_kernel(const float* __restrict__ W1, const float* __restrict__ W2,
                                const float* __restrict__ W3, const float* __restrict__ Wo,
                                const float* __restrict__ b3, const float* __restrict__ bo,
                                uint2* __restrict__ wt1f, uint2* __restrict__ wt2f,
                                uint2* __restrict__ wtff, float* __restrict__ bf) {
    int i = blockIdx.x * blockDim.x + threadIdx.x;
    if (i < 8192) {                         // wt1f / wt2f (4096 slots each)
        const float* W = (i < 4096) ? W1 : W2;
        uint2* out = (i < 4096) ? wt1f : wt2f;
        int s = i & 4095;
        int lane = s & 31, nt = (s >> 5) & 7, ks = (s >> 8) & 7, wc = s >> 11;
        int n  = wc * 64 + nt * 8 + (lane >> 2);
        int k0 = ks * 16 + 2 * (lane & 3);
        uint2 v;
        *(half2*)&v.x = __floats2half2_rn(W[k0 * 128 + n], W[(k0 + 1) * 128 + n]);
        *(half2*)&v.y = __floats2half2_rn(W[(k0 + 8) * 128 + n], W[(k0 + 9) * 128 + n]);
        out[s] = v;
    } else if (i < 8192 + 2048) {           // wtff: fused W3@Wout, N=64
        int s = i - 8192;
        int lane = s & 31, nt = (s >> 5) & 7, ks = (s >> 8) & 7;
        int n  = nt * 8 + (lane >> 2);
        int k0 = ks * 16 + 2 * (lane & 3);
        float f[4];
#pragma unroll
        for (int m = 0; m < 4; ++m) {
            int k = k0 + (m & 1) + (m >> 1) * 8;   // k0, k0+1, k0+8, k0+9
            float acc = 0.f;
#pragma unroll 8
            for (int q = 0; q < 128; ++q) acc += W3[k * 128 + q] * Wo[q * 64 + n];
            f[m] = acc;
        }
        uint2 v;
        *(half2*)&v.x = __floats2half2_rn(f[0], f[1]);
        *(half2*)&v.y = __floats2half2_rn(f[2], f[3]);
        wtff[s] = v;
    } else if (i < 8192 + 2048 + 64) {      // bf
        int c = i - 8192 - 2048;
        float acc = bo[c];
#pragma unroll 8
        for (int q = 0; q < 128; ++q) acc += b3[q] * Wo[q * 64 + c];
        bf[c] = acc;
    }
}

// ---------------- aggregation: warp per node, CSR gather (simple loop) ------------
template <bool RELU>
__global__ void agg_kernel(const __half* __restrict__ t, const int* __restrict__ rowptr,
                           const int2* __restrict__ epack, const float* __restrict__ isq,
                           const float* __restrict__ bias, __half* __restrict__ out, int n) {
    int node = (blockIdx.x * blockDim.x + threadIdx.x) >> 5;
    if (node >= n) return;
    int lane = threadIdx.x & 31;
    int beg = rowptr[node], end = rowptr[node + 1];
    float s = isq[node], c = s * s;

    uint2 raw = __ldg((const uint2*)(t + (size_t)node * FDIM) + lane);
    float2 f0 = __half22float2(*(half2*)&raw.x);
    float2 f1 = __half22float2(*(half2*)&raw.y);
    float4 acc = make_float4(c * f0.x, c * f0.y, c * f1.x, c * f1.y);

    for (int j = beg; j < end; ++j) {
        int2 p = __ldg(&epack[j]);
        float w = __int_as_float(p.y);
        uint2 r2 = __ldg((const uint2*)(t + (size_t)p.x * FDIM) + lane);
        float2 g0 = __half22float2(*(half2*)&r2.x);
        float2 g1 = __half22float2(*(half2*)&r2.y);
        acc.x += w * g0.x; acc.y += w * g0.y; acc.z += w * g1.x; acc.w += w * g1.y;
    }
    float4 b = __ldg((const float4*)bias + lane);
    acc.x += b.x; acc.y += b.y; acc.z += b.z; acc.w += b.w;
    if (RELU) {
        acc.x = fmaxf(acc.x, 0.f); acc.y = fmaxf(acc.y, 0.f);
        acc.z = fmaxf(acc.z, 0.f); acc.w = fmaxf(acc.w, 0.f);
    }
    uint2 o;
    *(half2*)&o.x = __floats2half2_rn(acc.x, acc.y);
    *(half2*)&o.y = __floats2half2_rn(acc.z, acc.w);
    ((uint2*)(out + (size_t)node * FDIM))[lane] = o;
}

// final agg: 64 features, fp32 output with fused bias (writes d_out directly)
__global__ void agg64_kernel(const __half* __restrict__ t, const int* __restrict__ rowptr,
                             const int2* __restrict__ epack, const float* __restrict__ isq,
                             const float* __restrict__ bias, float* __restrict__ out, int n) {
    int node = (blockIdx.x * blockDim.x + threadIdx.x) >> 5;
    if (node >= n) return;
    int lane = threadIdx.x & 31;
    int beg = rowptr[node], end = rowptr[node + 1];
    float s = isq[node], c = s * s;

    uint32_t raw = __ldg((const uint32_t*)(t + (size_t)node * 64) + lane);
    float2 f = __half22float2(*(half2*)&raw);
    float2 acc = make_float2(c * f.x, c * f.y);

    for (int j = beg; j < end; ++j) {
        int2 p = __ldg(&epack[j]);
        float w = __int_as_float(p.y);
        uint32_t r2 = __ldg((const uint32_t*)(t + (size_t)p.x * 64) + lane);
        float2 g = __half22float2(*(half2*)&r2);
        acc.x += w * g.x; acc.y += w * g.y;
    }
    float2 b = __ldg((const float2*)bias + lane);
    acc.x += b.x; acc.y += b.y;
    ((float2*)(out + (size_t)node * 64))[lane] = acc;
}

// ---------------- fp16 mma helper ----------------
__device__ __forceinline__ void mma_16n8k16(float& c0, float& c1, float& c2, float& c3,
                                            uint32_t a0, uint32_t a1, uint32_t a2, uint32_t a3,
                                            uint32_t b0, uint32_t b1) {
    asm volatile(
        "mma.sync.aligned.m16n8k16.row.col.f32.f16.f16.f32 "
        "{%0,%1,%2,%3}, {%4,%5,%6,%7}, {%8,%9}, {%0,%1,%2,%3};"
        : "+f"(c0), "+f"(c1), "+f"(c2), "+f"(c3)
        : "r"(a0), "r"(a1), "r"(a2), "r"(a3), "r"(b0), "r"(b1));
}

// ---------------- persistent GEMM: C(half) = A[M,128] @ W -------------------------
// W fragments staged ONCE per block (fragment-major: one LDS.64 per (ks,nt)).
template <int N_OUT, bool A_FP32>
__global__ __launch_bounds__(256, 4)
void gemm_mma_kernel(const void* __restrict__ Ain, const uint2* __restrict__ Wfrag,
                     __half* __restrict__ C, int M, int ntiles) {
    constexpr int COLG = N_OUT / 64;
    constexpr int ROWG = 8 / COLG;
    constexpr int BM   = ROWG * 16;
    constexpr int AST  = 136;
    constexpr int NT   = 8;
    constexpr int BSLOTS = COLG * 2048;     // uint2 slots

    extern __shared__ __half smem_h[];
    __half* As = smem_h;                    // [BM][AST]
    uint2* Bf  = (uint2*)(smem_h + BM * AST);  // [BSLOTS]

    int tid  = threadIdx.x;
    int wid  = tid >> 5;
    int lane = tid & 31;
    int g    = lane >> 2;
    int t4   = lane & 3;
    int wid_r = wid / COLG;
    int wid_c = wid % COLG;
    const int ncol0 = wid_c * 64;

    // stage W fragments once per block (straight uint4 copy)
    for (int i = tid; i < BSLOTS / 2; i += 256)
        ((uint4*)Bf)[i] = ((const uint4*)Wfrag)[i];

    for (int tile = blockIdx.x; tile < ntiles; tile += gridDim.x) {
        int row0 = tile * BM;

        __syncthreads();   // W ready (1st iter); prior compute done before As overwrite
        for (int i = tid; i < BM * 32; i += 256) {
            int r  = i >> 5;
            int c4 = i & 31;
            int gr = row0 + r;
            uint2 v = make_uint2(0u, 0u);
            if (gr < M) {
                if (A_FP32) {
                    float4 f = ((const float4*)((const float*)Ain + (size_t)gr * FDIM))[c4];
                    *(half2*)&v.x = __floats2half2_rn(f.x, f.y);
                    *(half2*)&v.y = __floats2half2_rn(f.z, f.w);
                } else {
                    v = ((const uint2*)((const __half*)Ain + (size_t)gr * FDIM))[c4];
                }
            }
            *(uint2*)(As + r * AST + c4 * 4) = v;
        }
        __syncthreads();

        float acc[NT][4];
#pragma unroll
        for (int nt = 0; nt < NT; ++nt) {
            acc[nt][0] = 0.f; acc[nt][1] = 0.f; acc[nt][2] = 0.f; acc[nt][3] = 0.f;
        }

        const __half* arow_lo = As + (wid_r * 16 + g) * AST;
        const __half* arow_hi = arow_lo + 8 * AST;

#pragma unroll
        for (int ks = 0; ks < 8; ++ks) {
            int k0 = ks * 16 + 2 * t4;
            uint32_t a0 = *(const uint32_t*)(arow_lo + k0);
            uint32_t a1 = *(const uint32_t*)(arow_hi + k0);
            uint32_t a2 = *(const uint32_t*)(arow_lo + k0 + 8);
            uint32_t a3 = *(const uint32_t*)(arow_hi + k0 + 8);
            const uint2* bk = Bf + wid_c * 2048 + ks * 256 + lane;
#pragma unroll
            for (int nt = 0; nt < NT; ++nt) {
                uint2 bb = bk[nt * 32];
                mma_16n8k16(acc[nt][0], acc[nt][1], acc[nt][2], acc[nt][3],
                            a0, a1, a2, a3, bb.x, bb.y);
            }
        }

        int r_lo = row0 + wid_r * 16 + g;
        int r_hi = r_lo + 8;
#pragma unroll
        for (int nt = 0; nt < NT; ++nt) {
            int col = ncol0 + nt * 8 + 2 * t4;
            if (r_lo < M)
                *(half2*)(C + (size_t)r_lo * N_OUT + col) = __floats2half2_rn(acc[nt][0], acc[nt][1]);
            if (r_hi < M)
                *(half2*)(C + (size_t)r_hi * N_OUT + col) = __floats2half2_rn(acc[nt][2], acc[nt][3]);
        }
    }
}

// ---------------- launch ----------------
extern "C" void kernel_launch(void* const* d_in, const int* in_sizes, int n_in,
                              void* d_out, int out_size) {
    const float* x   = (const float*)d_in[0];
    const int*   ei  = (const int*)d_in[1];     // int32 (JAX x64 disabled)
    const float* W1  = (const float*)d_in[2];
    const float* b1  = (const float*)d_in[3];
    const float* W2  = (const float*)d_in[4];
    const float* b2  = (const float*)d_in[5];
    const float* W3  = (const float*)d_in[6];
    const float* b3  = (const float*)d_in[7];
    const float* Wo  = (const float*)d_in[8];
    const float* bo  = (const float*)d_in[9];

    int n = in_sizes[0] / FDIM;
    int E = in_sizes[1] / 2;
    const int* src = ei;
    const int* dst = ei + E;

    __half *hA, *hB;
    uint2 *wt1f, *wt2f, *wtff;
    float *isq, *bf;
    int *cnt, *lpos, *rowptr, *partial;
    int2* epack;
    cudaGetSymbolAddress((void**)&hA,      g_hA);
    cudaGetSymbolAddress((void**)&hB,      g_hB);
    cudaGetSymbolAddress((void**)&isq,     g_isq);
    cudaGetSymbolAddress((void**)&cnt,     g_cnt);
    cudaGetSymbolAddress((void**)&lpos,    g_lpos);
    cudaGetSymbolAddress((void**)&rowptr,  g_rowptr);
    cudaGetSymbolAddress((void**)&partial, g_partial);
    cudaGetSymbolAddress((void**)&epack,   g_epack);
    cudaGetSymbolAddress((void**)&wt1f,    g_wt1f);
    cudaGetSymbolAddress((void**)&wt2f,    g_wt2f);
    cudaGetSymbolAddress((void**)&wtff,    g_wtff);
    cudaGetSymbolAddress((void**)&bf,      g_bf);

    // smem: As + Bfrag: N=128: 17408+32768=50176; N=64: 34816+16384=51200
    const int SMEM = 51200;
    cudaFuncSetAttribute(gemm_mma_kernel<128, true>,  cudaFuncAttributeMaxDynamicSharedMemorySize, SMEM);
    cudaFuncSetAttribute(gemm_mma_kernel<128, false>, cudaFuncAttributeMaxDynamicSharedMemorySize, SMEM);
    cudaFuncSetAttribute(gemm_mma_kernel<64, false>,  cudaFuncAttributeMaxDynamicSharedMemorySize, SMEM);

    const int T = 256;
    int nb_nodes   = (n + T - 1) / T;
    int nb_agg     = (int)(((long long)n * 32 + T - 1) / T);
    int nt128      = (n + 63) / 64;
    int nt64       = (n + 127) / 128;
    int nb_scan    = (n + SCAN_B - 1) / SCAN_B;
    const int PERSIST = 148 * 4;
    int gb128 = nt128 < PERSIST ? nt128 : PERSIST;
    int gb64  = nt64  < PERSIST ? nt64  : PERSIST;
    bool vec4 = (E % 4) == 0;   // int4 alignment of dst = ei + E requires E%4==0
    int E4 = E / 4;

    // ---- fork a side stream: {prep_all -> gemm1} || CSR chain ----
    cudaStream_t s2;
    cudaStreamCreateWithFlags(&s2, cudaStreamNonBlocking);
    cudaEvent_t evFork, evJoin;
    cudaEventCreateWithFlags(&evFork, cudaEventDisableTiming);
    cudaEventCreateWithFlags(&evJoin, cudaEventDisableTiming);

    cudaEventRecord(evFork, 0);
    cudaStreamWaitEvent(s2, evFork, 0);

    // side branch: weight prep + layer-1 GEMM (independent of edges)
    prep_all_kernel<<<(8192 + 2048 + 64 + T - 1) / T, T, 0, s2>>>(W1, W2, W3, Wo, b3, bo,
                                                                   wt1f, wt2f, wtff, bf);
    gemm_mma_kernel<128, true><<<gb128, 256, SMEM, s2>>>(x, wt1f, hA, n, nt128);
    cudaEventRecord(evJoin, s2);

    // main branch: CSR build + normalization
    zero_kernel<<<nb_nodes, T>>>(cnt, n);
    if (vec4) count4_kernel<<<(E4 + T - 1) / T, T>>>(dst, cnt, lpos, E4);
    else      count_kernel<<<(E + T - 1) / T, T>>>(dst, cnt, lpos, E);
    block_scan_kernel<<<nb_scan, SCAN_B>>>(cnt, rowptr, partial, isq, n);
    partial_scan_kernel<<<1, 32>>>(partial, nb_scan);
    add_offsets_kernel<<<nb_nodes, T>>>(rowptr, partial, n, nb_scan);
    if (vec4) fill4_kernel<<<(E4 + T - 1) / T, T>>>(src, dst, isq, rowptr, lpos, epack, E4);
    else      fill_kernel<<<(E + T - 1) / T, T>>>(src, dst, isq, rowptr, lpos, epack, E);

    // join: agg1 needs both gemm1 (s2) and fill (main)
    cudaStreamWaitEvent(0, evJoin, 0);

    // ---- layer 1 agg: h1 = relu(agg(x@W1) + b1) ----
    agg_kernel<true><<<nb_agg, T>>>(hA, rowptr, epack, isq, b1, hB, n);
    // ---- layer 2 ----
    gemm_mma_kernel<128, false><<<gb128, 256, SMEM>>>(hB, wt2f, hA, n, nt128);
    agg_kernel<true><<<nb_agg, T>>>(hA, rowptr, epack, isq, b2, hB, n);
    // ---- layer 3 + output fused ----
    gemm_mma_kernel<64, false><<<gb64, 256, SMEM>>>(hB, wtff, hA, n, nt64);
    agg64_kernel<<<nb_agg, T>>>(hA, rowptr, epack, isq, bf, (float*)d_out, n);
}

// round 17
// speedup vs baseline: 1.0050x; 1.0050x over previous
#include <cuda_runtime.h>
#include <cuda_fp16.h>
#include <cstdint>

#define FDIM 128
#define MAX_NODES 100000
#define MAX_EDGES 1600000
#define SCAN_B 1024
#define MAX_SCAN_BLOCKS ((MAX_NODES + SCAN_B - 1) / SCAN_B)

// ---------------- scratch (device globals: allocation-free rule) ----------------
__device__ __align__(16) __half g_hA[(size_t)MAX_NODES * FDIM];
__device__ __align__(16) __half g_hB[(size_t)MAX_NODES * FDIM];
__device__ float g_isq[MAX_NODES];
__device__ int   g_cnt[MAX_NODES];
__device__ int   g_lpos[MAX_EDGES];
__device__ int   g_rowptr[MAX_NODES + 1];
__device__ int   g_partial[MAX_SCAN_BLOCKS + 1];
__device__ int2  g_epack[MAX_EDGES];
// fragment-major B images: slot[(wc,ks,nt,lane)] = uint2{b0,b1}
__device__ __align__(16) uint2 g_wt1f[4096];   // N=128: 2*8*8*32
__device__ __align__(16) uint2 g_wt2f[4096];
__device__ __align__(16) uint2 g_wtff[2048];   // N=64 (fused W3@Wout)
__device__ float g_bf[64];                      // fused b3@Wout + bout

// ---------------- CSR build ----------------
__global__ void zero_kernel(int* __restrict__ cnt, int n) {
    int i = blockIdx.x * blockDim.x + threadIdx.x;
    if (i < n) cnt[i] = 0;
}
// scalar fallback
__global__ void count_kernel(const int* __restrict__ dst, int* __restrict__ cnt,
                             int* __restrict__ lpos, int E) {
    int e = blockIdx.x * blockDim.x + threadIdx.x;
    if (e < E) lpos[e] = atomicAdd(&cnt[dst[e]], 1);
}
// 4 edges/thread: int4 loads, 4 independent atomics
__global__ void count4_kernel(const int* __restrict__ dst, int* __restrict__ cnt,
                              int* __restrict__ lpos, int E4) {
    int i = blockIdx.x * blockDim.x + threadIdx.x;
    if (i >= E4) return;
    int4 d = ((const int4*)dst)[i];
    int p0 = atomicAdd(&cnt[d.x], 1);
    int p1 = atomicAdd(&cnt[d.y], 1);
    int p2 = atomicAdd(&cnt[d.z], 1);
    int p3 = atomicAdd(&cnt[d.w], 1);
    ((int4*)lpos)[i] = make_int4(p0, p1, p2, p3);
}
// block scan + isq fused (both read cnt)
__global__ void block_scan_kernel(const int* __restrict__ cnt, int* __restrict__ rowptr,
                                  int* __restrict__ partial, float* __restrict__ isq, int n) {
    __shared__ int sh[SCAN_B];
    int i = blockIdx.x * SCAN_B + threadIdx.x;
    int v = (i < n) ? cnt[i] : 0;
    if (i < n) isq[i] = rsqrtf((float)(v + 1));
    sh[threadIdx.x] = v;
    __syncthreads();
#pragma unroll
    for (int off = 1; off < SCAN_B; off <<= 1) {
        int t = (threadIdx.x >= off) ? sh[threadIdx.x - off] : 0;
        __syncthreads();
        sh[threadIdx.x] += t;
        __syncthreads();
    }
    if (i < n) rowptr[i] = sh[threadIdx.x] - v;
    if (threadIdx.x == SCAN_B - 1) partial[blockIdx.x] = sh[SCAN_B - 1];
}
__global__ void partial_scan_kernel(int* __restrict__ partial, int nb) {
    int lane = threadIdx.x;   // 32 threads
    int base = lane * 4;
    int v0 = (base + 0 < nb) ? partial[base + 0] : 0;
    int v1 = (base + 1 < nb) ? partial[base + 1] : 0;
    int v2 = (base + 2 < nb) ? partial[base + 2] : 0;
    int v3 = (base + 3 < nb) ? partial[base + 3] : 0;
    int tot = v0 + v1 + v2 + v3;
    int x = tot;
#pragma unroll
    for (int off = 1; off < 32; off <<= 1) {
        int y = __shfl_up_sync(0xFFFFFFFF, x, off);
        if (lane >= off) x += y;
    }
    int run = x - tot;
    if (base + 0 < nb) partial[base + 0] = run;            run += v0;
    if (base + 1 < nb) partial[base + 1] = run;            run += v1;
    if (base + 2 < nb) partial[base + 2] = run;            run += v2;
    if (base + 3 < nb) partial[base + 3] = run;
    if (lane == 31) partial[nb] = x;
}
__global__ void add_offsets_kernel(int* __restrict__ rowptr, const int* __restrict__ partial,
                                   int n, int nb) {
    int i = blockIdx.x * blockDim.x + threadIdx.x;
    if (i < n) rowptr[i] += partial[i / SCAN_B];
    if (i == 0) rowptr[n] = partial[nb];
}
// scalar fallback
__global__ void fill_kernel(const int* __restrict__ src, const int* __restrict__ dst,
                            const float* __restrict__ isq, const int* __restrict__ rowptr,
                            const int* __restrict__ lpos, int2* __restrict__ epack, int E) {
    int e = blockIdx.x * blockDim.x + threadIdx.x;
    if (e >= E) return;
    int s = src[e], d = dst[e];
    epack[rowptr[d] + lpos[e]] = make_int2(s, __float_as_int(isq[s] * isq[d]));
}
// 4 edges/thread
__global__ void fill4_kernel(const int* __restrict__ src, const int* __restrict__ dst,
                             const float* __restrict__ isq, const int* __restrict__ rowptr,
                             const int* __restrict__ lpos, int2* __restrict__ epack, int E4) {
    int i = blockIdx.x * blockDim.x + threadIdx.x;
    if (i >= E4) return;
    int4 s4 = ((const int4*)src)[i];
    int4 d4 = ((const int4*)dst)[i];
    int4 l4 = ((const int4*)lpos)[i];
    epack[rowptr[d4.x] + l4.x] = make_int2(s4.x, __float_as_int(isq[s4.x] * isq[d4.x]));
    epack[rowptr[d4.y] + l4.y] = make_int2(s4.y, __float_as_int(isq[s4.y] * isq[d4.y]));
    epack[rowptr[d4.z] + l4.z] = make_int2(s4.z, __float_as_int(isq[s4.z] * isq[d4.z]));
    epack[rowptr[d4.w] + l4.w] = make_int2(s4.w, __float_as_int(isq[s4.w] * isq[d4.w]));
}

// ---------------- W prep: build fragment-major images --------------------------
__global__ void prep_all_kernel(const float* __restrict__ W1, const float* __restrict__ W2,
                                const float* __restrict__ W3, const float* __restrict__ Wo,
                                const float* __restrict__ b3, const float* __restrict__ bo,
                                uint2* __restrict__ wt1f, uint2* __restrict__ wt2f,
                                uint2* __restrict__ wtff, float* __restrict__ bf) {
    int i = blockIdx.x * blockDim.x + threadIdx.x;
    if (i < 8192) {                         // wt1f / wt2f (4096 slots each)
        const float* W = (i < 4096) ? W1 : W2;
        uint2* out = (i < 4096) ? wt1f : wt2f;
        int s = i & 4095;
        int lane = s & 31, nt = (s >> 5) & 7, ks = (s >> 8) & 7, wc = s >> 11;
        int n  = wc * 64 + nt * 8 + (lane >> 2);
        int k0 = ks * 16 + 2 * (lane & 3);
        uint2 v;
        *(half2*)&v.x = __floats2half2_rn(W[k0 * 128 + n], W[(k0 + 1) * 128 + n]);
        *(half2*)&v.y = __floats2half2_rn(W[(k0 + 8) * 128 + n], W[(k0 + 9) * 128 + n]);
        out[s] = v;
    } else if (i < 8192 + 2048) {           // wtff: fused W3@Wout, N=64
        int s = i - 8192;
        int lane = s & 31, nt = (s >> 5) & 7, ks = (s >> 8) & 7;
        int n  = nt * 8 + (lane >> 2);
        int k0 = ks * 16 + 2 * (lane & 3);
        float f[4];
#pragma unroll
        for (int m = 0; m < 4; ++m) {
            int k = k0 + (m & 1) + (m >> 1) * 8;   // k0, k0+1, k0+8, k0+9
            float acc = 0.f;
#pragma unroll 8
            for (int q = 0; q < 128; ++q) acc += W3[k * 128 + q] * Wo[q * 64 + n];
            f[m] = acc;
        }
        uint2 v;
        *(half2*)&v.x = __floats2half2_rn(f[0], f[1]);
        *(half2*)&v.y = __floats2half2_rn(f[2], f[3]);
        wtff[s] = v;
    } else if (i < 8192 + 2048 + 64) {      // bf
        int c = i - 8192 - 2048;
        float acc = bo[c];
#pragma unroll 8
        for (int q = 0; q < 128; ++q) acc += b3[q] * Wo[q * 64 + c];
        bf[c] = acc;
    }
}

// ---------------- aggregation: warp per node, CSR gather (simple loop) ------------
template <bool RELU>
__global__ void agg_kernel(const __half* __restrict__ t, const int* __restrict__ rowptr,
                           const int2* __restrict__ epack, const float* __restrict__ isq,
                           const float* __restrict__ bias, __half* __restrict__ out, int n) {
    int node = (blockIdx.x * blockDim.x + threadIdx.x) >> 5;
    if (node >= n) return;
    int lane = threadIdx.x & 31;
    int beg = rowptr[node], end = rowptr[node + 1];
    float s = isq[node], c = s * s;

    uint2 raw = __ldg((const uint2*)(t + (size_t)node * FDIM) + lane);
    float2 f0 = __half22float2(*(half2*)&raw.x);
    float2 f1 = __half22float2(*(half2*)&raw.y);
    float4 acc = make_float4(c * f0.x, c * f0.y, c * f1.x, c * f1.y);

    for (int j = beg; j < end; ++j) {
        int2 p = __ldg(&epack[j]);
        float w = __int_as_float(p.y);
        uint2 r2 = __ldg((const uint2*)(t + (size_t)p.x * FDIM) + lane);
        float2 g0 = __half22float2(*(half2*)&r2.x);
        float2 g1 = __half22float2(*(half2*)&r2.y);
        acc.x += w * g0.x; acc.y += w * g0.y; acc.z += w * g1.x; acc.w += w * g1.y;
    }
    float4 b = __ldg((const float4*)bias + lane);
    acc.x += b.x; acc.y += b.y; acc.z += b.z; acc.w += b.w;
    if (RELU) {
        acc.x = fmaxf(acc.x, 0.f); acc.y = fmaxf(acc.y, 0.f);
        acc.z = fmaxf(acc.z, 0.f); acc.w = fmaxf(acc.w, 0.f);
    }
    uint2 o;
    *(half2*)&o.x = __floats2half2_rn(acc.x, acc.y);
    *(half2*)&o.y = __floats2half2_rn(acc.z, acc.w);
    ((uint2*)(out + (size_t)node * FDIM))[lane] = o;
}

// final agg: 64 features, fp32 output with fused bias (writes d_out directly)
__global__ void agg64_kernel(const __half* __restrict__ t, const int* __restrict__ rowptr,
                             const int2* __restrict__ epack, const float* __restrict__ isq,
                             const float* __restrict__ bias, float* __restrict__ out, int n) {
    int node = (blockIdx.x * blockDim.x + threadIdx.x) >> 5;
    if (node >= n) return;
    int lane = threadIdx.x & 31;
    int beg = rowptr[node], end = rowptr[node + 1];
    float s = isq[node], c = s * s;

    uint32_t raw = __ldg((const uint32_t*)(t + (size_t)node * 64) + lane);
    float2 f = __half22float2(*(half2*)&raw);
    float2 acc = make_float2(c * f.x, c * f.y);

    for (int j = beg; j < end; ++j) {
        int2 p = __ldg(&epack[j]);
        float w = __int_as_float(p.y);
        uint32_t r2 = __ldg((const uint32_t*)(t + (size_t)p.x * 64) + lane);
        float2 g = __half22float2(*(half2*)&r2);
        acc.x += w * g.x; acc.y += w * g.y;
    }
    float2 b = __ldg((const float2*)bias + lane);
    acc.x += b.x; acc.y += b.y;
    ((float2*)(out + (size_t)node * 64))[lane] = acc;
}

// ---------------- fp16 mma helper ----------------
__device__ __forceinline__ void mma_16n8k16(float& c0, float& c1, float& c2, float& c3,
                                            uint32_t a0, uint32_t a1, uint32_t a2, uint32_t a3,
                                            uint32_t b0, uint32_t b1) {
    asm volatile(
        "mma.sync.aligned.m16n8k16.row.col.f32.f16.f16.f32 "
        "{%0,%1,%2,%3}, {%4,%5,%6,%7}, {%8,%9}, {%0,%1,%2,%3};"
        : "+f"(c0), "+f"(c1), "+f"(c2), "+f"(c3)
        : "r"(a0), "r"(a1), "r"(a2), "r"(a3), "r"(b0), "r"(b1));
}

// ---------------- persistent GEMM: C(half) = A[M,128] @ W -------------------------
// 3 CTAs/SM (not 4): leaves ~16K regs + 74KB smem free per SM so CSR kernels can
// co-reside and the graph's parallel branch actually overlaps.
template <int N_OUT, bool A_FP32>
__global__ __launch_bounds__(256, 3)
void gemm_mma_kernel(const void* __restrict__ Ain, const uint2* __restrict__ Wfrag,
                     __half* __restrict__ C, int M, int ntiles) {
    constexpr int COLG = N_OUT / 64;
    constexpr int ROWG = 8 / COLG;
    constexpr int BM   = ROWG * 16;
    constexpr int AST  = 136;
    constexpr int NT   = 8;
    constexpr int BSLOTS = COLG * 2048;     // uint2 slots

    extern __shared__ __half smem_h[];
    __half* As = smem_h;                    // [BM][AST]
    uint2* Bf  = (uint2*)(smem_h + BM * AST);  // [BSLOTS]

    int tid  = threadIdx.x;
    int wid  = tid >> 5;
    int lane = tid & 31;
    int g    = lane >> 2;
    int t4   = lane & 3;
    int wid_r = wid / COLG;
    int wid_c = wid % COLG;
    const int ncol0 = wid_c * 64;

    // stage W fragments once per block (straight uint4 copy)
    for (int i = tid; i < BSLOTS / 2; i += 256)
        ((uint4*)Bf)[i] = ((const uint4*)Wfrag)[i];

    for (int tile = blockIdx.x; tile < ntiles; tile += gridDim.x) {
        int row0 = tile * BM;

        __syncthreads();   // W ready (1st iter); prior compute done before As overwrite
        for (int i = tid; i < BM * 32; i += 256) {
            int r  = i >> 5;
            int c4 = i & 31;
            int gr = row0 + r;
            uint2 v = make_uint2(0u, 0u);
            if (gr < M) {
                if (A_FP32) {
                    float4 f = ((const float4*)((const float*)Ain + (size_t)gr * FDIM))[c4];
                    *(half2*)&v.x = __floats2half2_rn(f.x, f.y);
                    *(half2*)&v.y = __floats2half2_rn(f.z, f.w);
                } else {
                    v = ((const uint2*)((const __half*)Ain + (size_t)gr * FDIM))[c4];
                }
            }
            *(uint2*)(As + r * AST + c4 * 4) = v;
        }
        __syncthreads();

        float acc[NT][4];
#pragma unroll
        for (int nt = 0; nt < NT; ++nt) {
            acc[nt][0] = 0.f; acc[nt][1] = 0.f; acc[nt][2] = 0.f; acc[nt][3] = 0.f;
        }

        const __half* arow_lo = As + (wid_r * 16 + g) * AST;
        const __half* arow_hi = arow_lo + 8 * AST;

#pragma unroll
        for (int ks = 0; ks < 8; ++ks) {
            int k0 = ks * 16 + 2 * t4;
            uint32_t a0 = *(const uint32_t*)(arow_lo + k0);
            uint32_t a1 = *(const uint32_t*)(arow_hi + k0);
            uint32_t a2 = *(const uint32_t*)(arow_lo + k0 + 8);
            uint32_t a3 = *(const uint32_t*)(arow_hi + k0 + 8);
            const uint2* bk = Bf + wid_c * 2048 + ks * 256 + lane;
#pragma unroll
            for (int nt = 0; nt < NT; ++nt) {
                uint2 bb = bk[nt * 32];
                mma_16n8k16(acc[nt][0], acc[nt][1], acc[nt][2], acc[nt][3],
                            a0, a1, a2, a3, bb.x, bb.y);
            }
        }

        int r_lo = row0 + wid_r * 16 + g;
        int r_hi = r_lo + 8;
#pragma unroll
        for (int nt = 0; nt < NT; ++nt) {
            int col = ncol0 + nt * 8 + 2 * t4;
            if (r_lo < M)
                *(half2*)(C + (size_t)r_lo * N_OUT + col) = __floats2half2_rn(acc[nt][0], acc[nt][1]);
            if (r_hi < M)
                *(half2*)(C + (size_t)r_hi * N_OUT + col) = __floats2half2_rn(acc[nt][2], acc[nt][3]);
        }
    }
}

// ---------------- launch ----------------
extern "C" void kernel_launch(void* const* d_in, const int* in_sizes, int n_in,
                              void* d_out, int out_size) {
    const float* x   = (const float*)d_in[0];
    const int*   ei  = (const int*)d_in[1];     // int32 (JAX x64 disabled)
    const float* W1  = (const float*)d_in[2];
    const float* b1  = (const float*)d_in[3];
    const float* W2  = (const float*)d_in[4];
    const float* b2  = (const float*)d_in[5];
    const float* W3  = (const float*)d_in[6];
    const float* b3  = (const float*)d_in[7];
    const float* Wo  = (const float*)d_in[8];
    const float* bo  = (const float*)d_in[9];

    int n = in_sizes[0] / FDIM;
    int E = in_sizes[1] / 2;
    const int* src = ei;
    const int* dst = ei + E;

    __half *hA, *hB;
    uint2 *wt1f, *wt2f, *wtff;
    float *isq, *bf;
    int *cnt, *lpos, *rowptr, *partial;
    int2* epack;
    cudaGetSymbolAddress((void**)&hA,      g_hA);
    cudaGetSymbolAddress((void**)&hB,      g_hB);
    cudaGetSymbolAddress((void**)&isq,     g_isq);
    cudaGetSymbolAddress((void**)&cnt,     g_cnt);
    cudaGetSymbolAddress((void**)&lpos,    g_lpos);
    cudaGetSymbolAddress((void**)&rowptr,  g_rowptr);
    cudaGetSymbolAddress((void**)&partial, g_partial);
    cudaGetSymbolAddress((void**)&epack,   g_epack);
    cudaGetSymbolAddress((void**)&wt1f,    g_wt1f);
    cudaGetSymbolAddress((void**)&wt2f,    g_wt2f);
    cudaGetSymbolAddress((void**)&wtff,    g_wtff);
    cudaGetSymbolAddress((void**)&bf,      g_bf);

    // smem: As + Bfrag: N=128: 17408+32768=50176; N=64: 34816+16384=51200
    const int SMEM = 51200;
    cudaFuncSetAttribute(gemm_mma_kernel<128, true>,  cudaFuncAttributeMaxDynamicSharedMemorySize, SMEM);
    cudaFuncSetAttribute(gemm_mma_kernel<128, false>, cudaFuncAttributeMaxDynamicSharedMemorySize, SMEM);
    cudaFuncSetAttribute(gemm_mma_kernel<64, false>,  cudaFuncAttributeMaxDynamicSharedMemorySize, SMEM);

    const int T = 256;
    int nb_nodes   = (n + T - 1) / T;
    int nb_agg     = (int)(((long long)n * 32 + T - 1) / T);
    int nt128      = (n + 63) / 64;
    int nt64       = (n + 127) / 128;
    int nb_scan    = (n + SCAN_B - 1) / SCAN_B;
    const int PERSIST = 148 * 3;         // 3 CTAs/SM -> leaves co-residency headroom
    int gb128 = nt128 < PERSIST ? nt128 : PERSIST;
    int gb64  = nt64  < PERSIST ? nt64  : PERSIST;
    bool vec4 = (E % 4) == 0;
    int E4 = E / 4;

    // ---- fork a side stream: {prep_all -> gemm1} || CSR chain ----
    cudaStream_t s2;
    cudaStreamCreateWithFlags(&s2, cudaStreamNonBlocking);
    cudaEvent_t evFork, evJoin;
    cudaEventCreateWithFlags(&evFork, cudaEventDisableTiming);
    cudaEventCreateWithFlags(&evJoin, cudaEventDisableTiming);

    cudaEventRecord(evFork, 0);
    cudaStreamWaitEvent(s2, evFork, 0);

    // side branch: weight prep + layer-1 GEMM (independent of edges)
    prep_all_kernel<<<(8192 + 2048 + 64 + T - 1) / T, T, 0, s2>>>(W1, W2, W3, Wo, b3, bo,
                                                                   wt1f, wt2f, wtff, bf);
    gemm_mma_kernel<128, true><<<gb128, 256, SMEM, s2>>>(x, wt1f, hA, n, nt128);
    cudaEventRecord(evJoin, s2);

    // main branch: CSR build + normalization (co-resident with gemm1 now)
    zero_kernel<<<nb_nodes, T>>>(cnt, n);
    if (vec4) count4_kernel<<<(E4 + T - 1) / T, T>>>(dst, cnt, lpos, E4);
    else      count_kernel<<<(E + T - 1) / T, T>>>(dst, cnt, lpos, E);
    block_scan_kernel<<<nb_scan, SCAN_B>>>(cnt, rowptr, partial, isq, n);
    partial_scan_kernel<<<1, 32>>>(partial, nb_scan);
    add_offsets_kernel<<<nb_nodes, T>>>(rowptr, partial, n, nb_scan);
    if (vec4) fill4_kernel<<<(E4 + T - 1) / T, T>>>(src, dst, isq, rowptr, lpos, epack, E4);
    else      fill_kernel<<<(E + T - 1) / T, T>>>(src, dst, isq, rowptr, lpos, epack, E);

    // join: agg1 needs both gemm1 (s2) and fill (main)
    cudaStreamWaitEvent(0, evJoin, 0);

    // ---- layer 1 agg: h1 = relu(agg(x@W1) + b1) ----
    agg_kernel<true><<<nb_agg, T>>>(hA, rowptr, epack, isq, b1, hB, n);
    // ---- layer 2 ----
    gemm_mma_kernel<128, false><<<gb128, 256, SMEM>>>(hB, wt2f, hA, n, nt128);
    agg_kernel<true><<<nb_agg, T>>>(hA, rowptr, epack, isq, b2, hB, n);
    // ---- layer 3 + output fused ----
    gemm_mma_kernel<64, false><<<gb64, 256, SMEM>>>(hB, wtff, hA, n, nt64);
    agg64_kernel<<<nb_agg, T>>>(hA, rowptr, epack, isq, bf, (float*)d_out, n);
}